// round 14
// baseline (speedup 1.0000x reference)
#include <cuda_runtime.h>
#include <cuda_fp16.h>
#include <math.h>
#include <stdint.h>

#define C_CLASSES 512
#define DDIM      1024
#define EPS_F     1e-30f
#define SCALE_F   50.0f
#define MAX_N     65536
#define NHBLK     64

// ---------------- scratch (device globals; no allocations allowed) ----------------
__device__ __half g_bh[C_CLASSES * DDIM];          // means fp16 (unscaled), [N][K]
__device__ __half g_ah[(size_t)MAX_N * DDIM];      // targets fp16, [M][K]
__device__ float  g_tinv[MAX_N];                   // 1/max(||t||,eps)
__device__ float  g_norm2[C_CLASSES];              // sum of squares of mean
__device__ int    g_hist_part[NHBLK * C_CLASSES];  // per-block partial histograms
__device__ int    g_cursor[C_CLASSES];
__device__ int    g_offsets[C_CLASSES + 1];
__device__ int    g_idx[MAX_N];

// ---------------- PTX helpers (sm_80+ baseline features only) ----------------
__device__ __forceinline__ uint32_t smem_u32(const void* p) {
    uint32_t a;
    asm("{ .reg .u64 t; cvta.to.shared.u64 t, %1; cvt.u32.u64 %0, t; }" : "=r"(a) : "l"(p));
    return a;
}
#define CP_ASYNC16(dst, src) \
    asm volatile("cp.async.cg.shared.global [%0], [%1], 16;" :: "r"((uint32_t)(dst)), "l"(src))
#define CP_COMMIT() asm volatile("cp.async.commit_group;" ::: "memory")
#define CP_WAIT(n)  asm volatile("cp.async.wait_group %0;" :: "n"(n) : "memory")

__device__ __forceinline__ void ldsm_x4(uint32_t* r, uint32_t addr) {
    asm volatile("ldmatrix.sync.aligned.m8n8.x4.shared.b16 {%0,%1,%2,%3}, [%4];"
                 : "=r"(r[0]), "=r"(r[1]), "=r"(r[2]), "=r"(r[3]) : "r"(addr));
}
__device__ __forceinline__ void mma16816(float* c, const uint32_t* a, const uint32_t* b) {
    asm volatile("mma.sync.aligned.m16n8k16.row.col.f32.f16.f16.f32 "
                 "{%0,%1,%2,%3}, {%4,%5,%6,%7}, {%8,%9}, {%0,%1,%2,%3};"
                 : "+f"(c[0]), "+f"(c[1]), "+f"(c[2]), "+f"(c[3])
                 : "r"(a[0]), "r"(a[1]), "r"(a[2]), "r"(a[3]), "r"(b[0]), "r"(b[1]));
}
// 128B-row XOR swizzle: 16B column index c ^= (row & 7)
#define SWZ(o) ((o) ^ (((o) >> 3) & 0x70))

// ---------------- histogram of labels (64 blocks, partials, no atomics/zeroing) ----
__global__ void count_kernel(const int* __restrict__ labels, int n) {
    __shared__ int hist[C_CLASSES];
    for (int i = threadIdx.x; i < C_CLASSES; i += blockDim.x) hist[i] = 0;
    __syncthreads();
    for (int i = blockIdx.x * blockDim.x + threadIdx.x; i < n; i += gridDim.x * blockDim.x)
        atomicAdd(&hist[labels[i]], 1);
    __syncthreads();
    for (int i = threadIdx.x; i < C_CLASSES; i += blockDim.x)
        g_hist_part[blockIdx.x * C_CLASSES + i] = hist[i];
}

// ---------------- sum partials + exclusive scan (1 block) + zero norm2 ----------------
__global__ void scan_kernel() {
    __shared__ int tmp[C_CLASSES];
    int t = threadIdx.x;
    int v = 0;
#pragma unroll 8
    for (int b = 0; b < NHBLK; b++) v += g_hist_part[b * C_CLASSES + t];
    tmp[t] = v;
    g_norm2[t] = 0.f;
    __syncthreads();
    for (int off = 1; off < C_CLASSES; off <<= 1) {
        int x = (t >= off) ? tmp[t - off] : 0;
        __syncthreads();
        tmp[t] += x;
        __syncthreads();
    }
    g_offsets[t] = tmp[t] - v;
    g_cursor[t]  = tmp[t] - v;
    if (t == C_CLASSES - 1) g_offsets[C_CLASSES] = tmp[t];
}

// ---------------- scatter row indices into class buckets (256 blocks) ----------------
__global__ void scatter_kernel(const int* __restrict__ labels, int n) {
    int i = blockIdx.x * blockDim.x + threadIdx.x;
    if (i < n) {
        int p = atomicAdd(&g_cursor[labels[i]], 1);
        g_idx[p] = i;
    }
}

// ---------------- class mean (half range): gather-sum + mean + fp16 B + norm2 ----------
// grid (256, 4), 256 threads; covers classes [cbase, cbase+256)
__global__ void __launch_bounds__(256) classmean_kernel(const float* __restrict__ ctx,
                                                        float* __restrict__ means_out,
                                                        int cbase) {
    const int c   = cbase + blockIdx.x;
    const int col = blockIdx.y * 256 + threadIdx.x;
    const int tid = threadIdx.x;
    const int beg = g_offsets[c];
    const int end = g_offsets[c + 1];

    float a0 = 0.f, a1 = 0.f, a2 = 0.f, a3 = 0.f;
    int i = beg;
    for (; i + 3 < end; i += 4) {
        int r0 = g_idx[i], r1 = g_idx[i + 1], r2 = g_idx[i + 2], r3 = g_idx[i + 3];
        a0 += ctx[(size_t)r0 * DDIM + col];
        a1 += ctx[(size_t)r1 * DDIM + col];
        a2 += ctx[(size_t)r2 * DDIM + col];
        a3 += ctx[(size_t)r3 * DDIM + col];
    }
    for (; i < end; i++) a0 += ctx[(size_t)g_idx[i] * DDIM + col];

    const float inv = 1.f / fmaxf((float)(end - beg), 1.f);
    const float m = ((a0 + a1) + (a2 + a3)) * inv;
    means_out[(size_t)c * DDIM + col] = m;
    g_bh[(size_t)c * DDIM + col] = __float2half_rn(m);

    float ss = m * m;
    __shared__ float red[8];
#pragma unroll
    for (int o = 16; o > 0; o >>= 1) ss += __shfl_xor_sync(0xffffffffu, ss, o);
    if ((tid & 31) == 0) red[tid >> 5] = ss;
    __syncthreads();
    if (tid == 0) {
        float tot = 0.f;
#pragma unroll
        for (int k = 0; k < 8; k++) tot += red[k];
        atomicAdd(&g_norm2[c], tot);
    }
}

// ---------------- fused: target fp16 convert + inverse norms (one warp per row) ----------------
__global__ void quant_a_kernel(const float4* __restrict__ tgt4, int n_tgt) {
    int w    = (blockIdx.x * blockDim.x + threadIdx.x) >> 5;
    int lane = threadIdx.x & 31;
    if (w >= n_tgt) return;
    const float4* row = tgt4 + (size_t)w * (DDIM / 4);
    uint2* hrow = (uint2*)(g_ah + (size_t)w * DDIM);
    float ss = 0.f;
#pragma unroll
    for (int j = 0; j < 8; j++) {
        int e4 = lane + 32 * j;
        float4 v = row[e4];
        ss += v.x * v.x + v.y * v.y + v.z * v.z + v.w * v.w;
        __half2 h0 = __floats2half2_rn(v.x, v.y);
        __half2 h1 = __floats2half2_rn(v.z, v.w);
        uint2 hu;
        hu.x = *reinterpret_cast<uint32_t*>(&h0);
        hu.y = *reinterpret_cast<uint32_t*>(&h1);
        hrow[e4] = hu;
    }
#pragma unroll
    for (int o = 16; o > 0; o >>= 1) ss += __shfl_xor_sync(0xffffffffu, ss, o);
    if (lane == 0) g_tinv[w] = 1.f / fmaxf(sqrtf(ss), EPS_F);
}

// ---------------- fp16 HMMA GEMM (measured R8 config, column-half param) ----------------
// CTA tile 128x128, 256 threads, 8 warps (4m x 2n), warp tile 32x64.
// K-chunk 64 (128B rows, SW128 swizzle), 3 stages of 32KB -> 2 CTAs/SM.
#define MT   128
#define NT   128
#define KC   64
#define NC   (DDIM / KC)             // 16
#define OFF_A    0
#define OFF_B    16384
#define STAGE    32768
#define NSTAGE   3
#define SMEM_BYTES (NSTAGE * STAGE + 1024)

__device__ __forceinline__ void load_chunk(uint32_t stage, int m0, int n0, int gk0, int tid) {
#pragma unroll
    for (int p = 0; p < 4; p++) {
        int i = tid + p * 256;
        int row = i >> 3, c16 = i & 7;
        uint32_t off = SWZ((uint32_t)row * 128 + (uint32_t)c16 * 16);
        CP_ASYNC16(stage + OFF_A + off,
                   (const char*)(g_ah + (size_t)(m0 + row) * DDIM + gk0) + c16 * 16);
    }
#pragma unroll
    for (int p = 0; p < 4; p++) {
        int i = tid + p * 256;
        int row = i >> 3, c16 = i & 7;
        uint32_t off = SWZ((uint32_t)row * 128 + (uint32_t)c16 * 16);
        CP_ASYNC16(stage + OFF_B + off,
                   (const char*)(g_bh + (size_t)(n0 + row) * DDIM + gk0) + c16 * 16);
    }
    CP_COMMIT();
}

__global__ void __launch_bounds__(256, 2) gemm_mma_kernel(float* __restrict__ out, int nbase) {
    extern __shared__ char dsm[];
    uint32_t sb = (smem_u32(dsm) + 1023) & ~1023u;

    const int tid  = threadIdx.x;
    const int wid  = tid >> 5;
    const int lane = tid & 31;
    const int wm   = wid >> 1;            // 0..3 (m)
    const int wn   = wid & 1;             // 0..1 (n)
    const int n0 = nbase + blockIdx.x * NT;
    const int m0 = blockIdx.y * MT;

    float acc[2][8][4];
#pragma unroll
    for (int a = 0; a < 2; a++)
#pragma unroll
        for (int b = 0; b < 8; b++)
#pragma unroll
            for (int c = 0; c < 4; c++) acc[a][b][c] = 0.f;

    // prologue: 2 chunks in flight
    load_chunk(sb + 0 * STAGE, m0, n0, 0, tid);
    load_chunk(sb + 1 * STAGE, m0, n0, KC, tid);

    // lane pieces
    const int a_r  = (lane & 15);
    const int a_kh = (lane >> 4);
    const int b_r  = (lane & 7) + ((lane >> 4) << 3);
    const int b_kh = (lane >> 3) & 1;

    int stg = 0;
    for (int c = 0; c < NC; c++) {
        if (c < NC - 1) CP_WAIT(1); else CP_WAIT(0);
        __syncthreads();
        uint32_t stage = sb + (uint32_t)stg * STAGE;

#pragma unroll
        for (int s = 0; s < 4; s++) {     // 4 k16 slices per 64-wide chunk
            uint32_t af[2][4], bf[4][4];
#pragma unroll
            for (int mt = 0; mt < 2; mt++) {
                int row = wm * 32 + mt * 16 + a_r;
                uint32_t c16 = (uint32_t)((s * 2 + a_kh) ^ (row & 7));
                ldsm_x4(af[mt], stage + OFF_A + (uint32_t)row * 128 + c16 * 16);
            }
#pragma unroll
            for (int nt = 0; nt < 4; nt++) {
                int row = wn * 64 + nt * 16 + b_r;
                uint32_t c16 = (uint32_t)((s * 2 + b_kh) ^ (row & 7));
                ldsm_x4(bf[nt], stage + OFF_B + (uint32_t)row * 128 + c16 * 16);
            }
            // 16 independent MMAs (acc reuse distance = 16)
#pragma unroll
            for (int mt = 0; mt < 2; mt++)
#pragma unroll
                for (int nt = 0; nt < 4; nt++) {
                    mma16816(acc[mt][nt * 2 + 0], af[mt], &bf[nt][0]);
                    mma16816(acc[mt][nt * 2 + 1], af[mt], &bf[nt][2]);
                }
        }

        if (c + 2 < NC) {
            int nstg = stg + 2; if (nstg >= NSTAGE) nstg -= NSTAGE;
            load_chunk(sb + (uint32_t)nstg * STAGE, m0, n0, (c + 2) * KC, tid);
        }
        if (++stg == NSTAGE) stg = 0;
    }

    // epilogue: out = acc * tinv[m] * (SCALE / max(||mean_n||, eps))
    const int qrow = lane >> 2;
    const int qcol = (lane & 3) * 2;
#pragma unroll
    for (int mt = 0; mt < 2; mt++) {
        int r0 = m0 + wm * 32 + mt * 16 + qrow;
        int r1 = r0 + 8;
        float t0 = g_tinv[r0], t1 = g_tinv[r1];
        float* p0 = out + (size_t)r0 * C_CLASSES + n0 + wn * 64 + qcol;
        float* p1 = out + (size_t)r1 * C_CLASSES + n0 + wn * 64 + qcol;
#pragma unroll
        for (int nf = 0; nf < 8; nf++) {
            int coln = n0 + wn * 64 + qcol + nf * 8;
            float sb0 = SCALE_F / fmaxf(sqrtf(g_norm2[coln]), EPS_F);
            float sb1 = SCALE_F / fmaxf(sqrtf(g_norm2[coln + 1]), EPS_F);
            float2 v0, v1;
            v0.x = acc[mt][nf][0] * t0 * sb0; v0.y = acc[mt][nf][1] * t0 * sb1;
            v1.x = acc[mt][nf][2] * t1 * sb0; v1.y = acc[mt][nf][3] * t1 * sb1;
            *(float2*)(p0 + nf * 8) = v0;
            *(float2*)(p1 + nf * 8) = v1;
        }
    }
}

// ---------------- launch: classmean/GEMM pipelined by column half ----------------
extern "C" void kernel_launch(void* const* d_in, const int* in_sizes, int n_in,
                              void* d_out, int out_size) {
    const float* ctx    = (const float*)d_in[0];
    const int*   labels = (const int*)d_in[1];
    const float* tgt    = (const float*)d_in[2];
    const int n_ctx = in_sizes[1];
    const int n_tgt = in_sizes[2] / DDIM;

    float* logits    = (float*)d_out;
    float* means_out = (float*)d_out + (size_t)n_tgt * C_CLASSES;

    static cudaStream_t s_side = nullptr, s_g0 = nullptr, s_g1 = nullptr;
    static cudaEvent_t  s_fork = nullptr, s_join = nullptr;
    static cudaEvent_t  ev_h0 = nullptr, ev_h1 = nullptr, ev_d0 = nullptr, ev_d1 = nullptr;
    if (!s_side) {
        cudaStreamCreateWithFlags(&s_side, cudaStreamNonBlocking);
        cudaStreamCreateWithFlags(&s_g0, cudaStreamNonBlocking);
        cudaStreamCreateWithFlags(&s_g1, cudaStreamNonBlocking);
        cudaEventCreateWithFlags(&s_fork, cudaEventDisableTiming);
        cudaEventCreateWithFlags(&s_join, cudaEventDisableTiming);
        cudaEventCreateWithFlags(&ev_h0, cudaEventDisableTiming);
        cudaEventCreateWithFlags(&ev_h1, cudaEventDisableTiming);
        cudaEventCreateWithFlags(&ev_d0, cudaEventDisableTiming);
        cudaEventCreateWithFlags(&ev_d1, cudaEventDisableTiming);
    }
    cudaFuncSetAttribute(gemm_mma_kernel, cudaFuncAttributeMaxDynamicSharedMemorySize, SMEM_BYTES);

    // fork: target fp16 convert runs concurrently with the class-means chain
    cudaEventRecord(s_fork, 0);
    cudaStreamWaitEvent(s_side, s_fork, 0);
    quant_a_kernel<<<(n_tgt + 7) / 8, 256, 0, s_side>>>((const float4*)tgt, n_tgt);
    cudaEventRecord(s_join, s_side);

    // label chain
    count_kernel<<<NHBLK, 256>>>(labels, n_ctx);
    scan_kernel<<<1, C_CLASSES>>>();
    scatter_kernel<<<(n_ctx + 255) / 256, 256>>>(labels, n_ctx);

    // class means, split in column halves; GEMM half g starts as soon as its classes are ready
    classmean_kernel<<<dim3(256, 4), 256>>>(ctx, means_out, 0);
    cudaEventRecord(ev_h0, 0);
    classmean_kernel<<<dim3(256, 4), 256>>>(ctx, means_out, 256);
    cudaEventRecord(ev_h1, 0);

    cudaStreamWaitEvent(s_g0, ev_h0, 0);
    cudaStreamWaitEvent(s_g0, s_join, 0);
    gemm_mma_kernel<<<dim3(2, n_tgt / MT), 256, SMEM_BYTES, s_g0>>>(logits, 0);
    cudaEventRecord(ev_d0, s_g0);

    cudaStreamWaitEvent(s_g1, ev_h1, 0);
    cudaStreamWaitEvent(s_g1, s_join, 0);
    gemm_mma_kernel<<<dim3(2, n_tgt / MT), 256, SMEM_BYTES, s_g1>>>(logits, 256);
    cudaEventRecord(ev_d1, s_g1);

    // join everything back to the origin stream (graph-capture requirement)
    cudaStreamWaitEvent(0, ev_d0, 0);
    cudaStreamWaitEvent(0, ev_d1, 0);
}

// round 15
// speedup vs baseline: 1.0290x; 1.0290x over previous
#include <cuda_runtime.h>
#include <cuda_fp16.h>
#include <math.h>
#include <stdint.h>

#define C_CLASSES 512
#define DDIM      1024
#define EPS_F     1e-30f
#define SCALE_F   50.0f
#define MAX_N     65536
#define NHBLK     64

// ---------------- scratch (device globals; no allocations allowed) ----------------
__device__ float  g_sums[C_CLASSES * DDIM];
__device__ __half g_bh[C_CLASSES * DDIM];          // scaled means fp16, [N][K]
__device__ __half g_ah[(size_t)MAX_N * DDIM];      // targets fp16, [M][K]
__device__ float  g_tinv[MAX_N];
__device__ int    g_hist_part[NHBLK * C_CLASSES];  // per-block partial histograms
__device__ int    g_counts_i[C_CLASSES];
__device__ int    g_cursor[C_CLASSES];
__device__ int    g_offsets[C_CLASSES + 1];
__device__ int    g_idx[MAX_N];

// ---------------- PTX helpers (sm_80+ baseline features only) ----------------
__device__ __forceinline__ uint32_t smem_u32(const void* p) {
    uint32_t a;
    asm("{ .reg .u64 t; cvta.to.shared.u64 t, %1; cvt.u32.u64 %0, t; }" : "=r"(a) : "l"(p));
    return a;
}
#define CP_ASYNC16(dst, src) \
    asm volatile("cp.async.cg.shared.global [%0], [%1], 16;" :: "r"((uint32_t)(dst)), "l"(src))
#define CP_COMMIT() asm volatile("cp.async.commit_group;" ::: "memory")
#define CP_WAIT(n)  asm volatile("cp.async.wait_group %0;" :: "n"(n) : "memory")

__device__ __forceinline__ void ldsm_x4(uint32_t* r, uint32_t addr) {
    asm volatile("ldmatrix.sync.aligned.m8n8.x4.shared.b16 {%0,%1,%2,%3}, [%4];"
                 : "=r"(r[0]), "=r"(r[1]), "=r"(r[2]), "=r"(r[3]) : "r"(addr));
}
__device__ __forceinline__ void mma16816(float* c, const uint32_t* a, const uint32_t* b) {
    asm volatile("mma.sync.aligned.m16n8k16.row.col.f32.f16.f16.f32 "
                 "{%0,%1,%2,%3}, {%4,%5,%6,%7}, {%8,%9}, {%0,%1,%2,%3};"
                 : "+f"(c[0]), "+f"(c[1]), "+f"(c[2]), "+f"(c[3])
                 : "r"(a[0]), "r"(a[1]), "r"(a[2]), "r"(a[3]), "r"(b[0]), "r"(b[1]));
}
// 128B-row XOR swizzle: 16B column index c ^= (row & 7)
#define SWZ(o) ((o) ^ (((o) >> 3) & 0x70))

// ---------------- histogram of labels (64 blocks, partials; no zeroing needed) ----
__global__ void count_kernel(const int* __restrict__ labels, int n) {
    __shared__ int hist[C_CLASSES];
    for (int i = threadIdx.x; i < C_CLASSES; i += blockDim.x) hist[i] = 0;
    __syncthreads();
    for (int i = blockIdx.x * blockDim.x + threadIdx.x; i < n; i += gridDim.x * blockDim.x)
        atomicAdd(&hist[labels[i]], 1);
    __syncthreads();
    for (int i = threadIdx.x; i < C_CLASSES; i += blockDim.x)
        g_hist_part[blockIdx.x * C_CLASSES + i] = hist[i];
}

// ---------------- sum partials + exclusive scan (1 block) ----------------
__global__ void scan_kernel() {
    __shared__ int tmp[C_CLASSES];
    int t = threadIdx.x;
    int v = 0;
#pragma unroll 8
    for (int b = 0; b < NHBLK; b++) v += g_hist_part[b * C_CLASSES + t];
    tmp[t] = v;
    g_counts_i[t] = v;
    __syncthreads();
    for (int off = 1; off < C_CLASSES; off <<= 1) {
        int x = (t >= off) ? tmp[t - off] : 0;
        __syncthreads();
        tmp[t] += x;
        __syncthreads();
    }
    g_offsets[t] = tmp[t] - v;
    g_cursor[t]  = tmp[t] - v;
    if (t == C_CLASSES - 1) g_offsets[C_CLASSES] = tmp[t];
}

// ---------------- scatter row indices into class buckets ----------------
__global__ void scatter_kernel(const int* __restrict__ labels, int n) {
    int i = blockIdx.x * blockDim.x + threadIdx.x;
    if (i < n) {
        int p = atomicAdd(&g_cursor[labels[i]], 1);
        g_idx[p] = i;
    }
}

// ---------------- per-class gather + register accumulation ----------------
__global__ void classsum_kernel(const float* __restrict__ ctx) {
    const int c   = blockIdx.x;
    const int col = blockIdx.y * 256 + threadIdx.x;
    const int beg = g_offsets[c];
    const int end = g_offsets[c + 1];

    float a0 = 0.f, a1 = 0.f, a2 = 0.f, a3 = 0.f;
    int i = beg;
    for (; i + 3 < end; i += 4) {
        int r0 = g_idx[i], r1 = g_idx[i + 1], r2 = g_idx[i + 2], r3 = g_idx[i + 3];
        a0 += ctx[(size_t)r0 * DDIM + col];
        a1 += ctx[(size_t)r1 * DDIM + col];
        a2 += ctx[(size_t)r2 * DDIM + col];
        a3 += ctx[(size_t)r3 * DDIM + col];
    }
    for (; i < end; i++) a0 += ctx[(size_t)g_idx[i] * DDIM + col];
    g_sums[(size_t)c * DDIM + col] = (a0 + a1) + (a2 + a3);
}

// ---------------- finalize: means -> d_out; scaled fp16 B -> g_bh ----------------
__global__ void finalize_kernel(float* __restrict__ means_out) {
    const int c   = blockIdx.x;
    const int tid = threadIdx.x;
    const float inv = 1.f / fmaxf((float)g_counts_i[c], 1.f);

    float m[4];
    float ss = 0.f;
#pragma unroll
    for (int j = 0; j < 4; j++) {
        int d = tid + 256 * j;
        float v = g_sums[(size_t)c * DDIM + d] * inv;
        m[j] = v;
        means_out[(size_t)c * DDIM + d] = v;
        ss += v * v;
    }
    __shared__ float red[8];
#pragma unroll
    for (int o = 16; o > 0; o >>= 1) ss += __shfl_xor_sync(0xffffffffu, ss, o);
    if ((tid & 31) == 0) red[tid >> 5] = ss;
    __syncthreads();
    __shared__ float s_scale;
    if (tid == 0) {
        float tot = 0.f;
#pragma unroll
        for (int k = 0; k < 8; k++) tot += red[k];
        s_scale = SCALE_F / fmaxf(sqrtf(tot), EPS_F);
    }
    __syncthreads();
    const float sc = s_scale;
#pragma unroll
    for (int j = 0; j < 4; j++) {
        int d = tid + 256 * j;
        g_bh[(size_t)c * DDIM + d] = __float2half_rn(m[j] * sc);
    }
}

// ---------------- fused: target fp16 convert + inverse norms (one warp per row) ----------------
__global__ void quant_a_kernel(const float4* __restrict__ tgt4, int n_tgt) {
    int w    = (blockIdx.x * blockDim.x + threadIdx.x) >> 5;
    int lane = threadIdx.x & 31;
    if (w >= n_tgt) return;
    const float4* row = tgt4 + (size_t)w * (DDIM / 4);
    uint2* hrow = (uint2*)(g_ah + (size_t)w * DDIM);
    float ss = 0.f;
#pragma unroll
    for (int j = 0; j < 8; j++) {
        int e4 = lane + 32 * j;
        float4 v = row[e4];
        ss += v.x * v.x + v.y * v.y + v.z * v.z + v.w * v.w;
        __half2 h0 = __floats2half2_rn(v.x, v.y);
        __half2 h1 = __floats2half2_rn(v.z, v.w);
        uint2 hu;
        hu.x = *reinterpret_cast<uint32_t*>(&h0);
        hu.y = *reinterpret_cast<uint32_t*>(&h1);
        hrow[e4] = hu;
    }
#pragma unroll
    for (int o = 16; o > 0; o >>= 1) ss += __shfl_xor_sync(0xffffffffu, ss, o);
    if (lane == 0) g_tinv[w] = 1.f / fmaxf(sqrtf(ss), EPS_F);
}

// ---------------- fp16 HMMA GEMM (measured 166us config): out = A B^T * tinv ----------------
// CTA tile 128x128, 256 threads, 8 warps (4m x 2n), warp tile 32x64.
// K-chunk 64 (128B rows, SW128 swizzle), 3 stages of 32KB -> 2 CTAs/SM.
#define MT   128
#define NT   128
#define KC   64
#define NC   (DDIM / KC)             // 16
#define OFF_A    0
#define OFF_B    16384
#define STAGE    32768
#define NSTAGE   3
#define SMEM_BYTES (NSTAGE * STAGE + 1024)

__device__ __forceinline__ void load_chunk(uint32_t stage, int m0, int n0, int gk0, int tid) {
#pragma unroll
    for (int p = 0; p < 4; p++) {
        int i = tid + p * 256;
        int row = i >> 3, c16 = i & 7;
        uint32_t off = SWZ((uint32_t)row * 128 + (uint32_t)c16 * 16);
        CP_ASYNC16(stage + OFF_A + off,
                   (const char*)(g_ah + (size_t)(m0 + row) * DDIM + gk0) + c16 * 16);
    }
#pragma unroll
    for (int p = 0; p < 4; p++) {
        int i = tid + p * 256;
        int row = i >> 3, c16 = i & 7;
        uint32_t off = SWZ((uint32_t)row * 128 + (uint32_t)c16 * 16);
        CP_ASYNC16(stage + OFF_B + off,
                   (const char*)(g_bh + (size_t)(n0 + row) * DDIM + gk0) + c16 * 16);
    }
    CP_COMMIT();
}

__global__ void __launch_bounds__(256, 2) gemm_mma_kernel(float* __restrict__ out) {
    extern __shared__ char dsm[];
    uint32_t sb = (smem_u32(dsm) + 1023) & ~1023u;

    const int tid  = threadIdx.x;
    const int wid  = tid >> 5;
    const int lane = tid & 31;
    const int wm   = wid >> 1;            // 0..3 (m)
    const int wn   = wid & 1;             // 0..1 (n)
    const int n0 = blockIdx.x * NT;
    const int m0 = blockIdx.y * MT;

    float acc[2][8][4];
#pragma unroll
    for (int a = 0; a < 2; a++)
#pragma unroll
        for (int b = 0; b < 8; b++)
#pragma unroll
            for (int c = 0; c < 4; c++) acc[a][b][c] = 0.f;

    // prologue: 2 chunks in flight
    load_chunk(sb + 0 * STAGE, m0, n0, 0, tid);
    load_chunk(sb + 1 * STAGE, m0, n0, KC, tid);

    // lane pieces
    const int a_r  = (lane & 15);
    const int a_kh = (lane >> 4);
    const int b_r  = (lane & 7) + ((lane >> 4) << 3);
    const int b_kh = (lane >> 3) & 1;

    int stg = 0;
    for (int c = 0; c < NC; c++) {
        if (c < NC - 1) CP_WAIT(1); else CP_WAIT(0);
        __syncthreads();
        uint32_t stage = sb + (uint32_t)stg * STAGE;

#pragma unroll
        for (int s = 0; s < 4; s++) {     // 4 k16 slices per 64-wide chunk
            uint32_t af[2][4], bf[4][4];
#pragma unroll
            for (int mt = 0; mt < 2; mt++) {
                int row = wm * 32 + mt * 16 + a_r;
                uint32_t c16 = (uint32_t)((s * 2 + a_kh) ^ (row & 7));
                ldsm_x4(af[mt], stage + OFF_A + (uint32_t)row * 128 + c16 * 16);
            }
#pragma unroll
            for (int nt = 0; nt < 4; nt++) {
                int row = wn * 64 + nt * 16 + b_r;
                uint32_t c16 = (uint32_t)((s * 2 + b_kh) ^ (row & 7));
                ldsm_x4(bf[nt], stage + OFF_B + (uint32_t)row * 128 + c16 * 16);
            }
            // 16 independent MMAs (acc reuse distance = 16)
#pragma unroll
            for (int mt = 0; mt < 2; mt++)
#pragma unroll
                for (int nt = 0; nt < 4; nt++) {
                    mma16816(acc[mt][nt * 2 + 0], af[mt], &bf[nt][0]);
                    mma16816(acc[mt][nt * 2 + 1], af[mt], &bf[nt][2]);
                }
        }

        if (c + 2 < NC) {
            int nstg = stg + 2; if (nstg >= NSTAGE) nstg -= NSTAGE;
            load_chunk(sb + (uint32_t)nstg * STAGE, m0, n0, (c + 2) * KC, tid);
        }
        if (++stg == NSTAGE) stg = 0;
    }

    // epilogue: scale by 1/||t|| and store
    const int qrow = lane >> 2;
    const int qcol = (lane & 3) * 2;
#pragma unroll
    for (int mt = 0; mt < 2; mt++) {
        int r0 = m0 + wm * 32 + mt * 16 + qrow;
        int r1 = r0 + 8;
        float t0 = g_tinv[r0], t1 = g_tinv[r1];
        float* p0 = out + (size_t)r0 * C_CLASSES + n0 + wn * 64 + qcol;
        float* p1 = out + (size_t)r1 * C_CLASSES + n0 + wn * 64 + qcol;
#pragma unroll
        for (int nf = 0; nf < 8; nf++) {
            float2 v0, v1;
            v0.x = acc[mt][nf][0] * t0; v0.y = acc[mt][nf][1] * t0;
            v1.x = acc[mt][nf][2] * t1; v1.y = acc[mt][nf][3] * t1;
            *(float2*)(p0 + nf * 8) = v0;
            *(float2*)(p1 + nf * 8) = v1;
        }
    }
}

// ---------------- launch (side-stream fork/join for prep overlap) ----------------
extern "C" void kernel_launch(void* const* d_in, const int* in_sizes, int n_in,
                              void* d_out, int out_size) {
    const float* ctx    = (const float*)d_in[0];
    const int*   labels = (const int*)d_in[1];
    const float* tgt    = (const float*)d_in[2];
    const int n_ctx = in_sizes[1];
    const int n_tgt = in_sizes[2] / DDIM;

    float* logits    = (float*)d_out;
    float* means_out = (float*)d_out + (size_t)n_tgt * C_CLASSES;

    static cudaStream_t s_side = nullptr;
    static cudaEvent_t  s_fork = nullptr, s_join = nullptr;
    if (!s_side) {
        cudaStreamCreateWithFlags(&s_side, cudaStreamNonBlocking);
        cudaEventCreateWithFlags(&s_fork, cudaEventDisableTiming);
        cudaEventCreateWithFlags(&s_join, cudaEventDisableTiming);
    }
    cudaFuncSetAttribute(gemm_mma_kernel, cudaFuncAttributeMaxDynamicSharedMemorySize, SMEM_BYTES);

    // fork: target fp16 convert runs concurrently with the class-means chain
    cudaEventRecord(s_fork, 0);
    cudaStreamWaitEvent(s_side, s_fork, 0);
    quant_a_kernel<<<(n_tgt + 7) / 8, 256, 0, s_side>>>((const float4*)tgt, n_tgt);
    cudaEventRecord(s_join, s_side);

    count_kernel<<<NHBLK, 256>>>(labels, n_ctx);
    scan_kernel<<<1, C_CLASSES>>>();
    scatter_kernel<<<(n_ctx + 255) / 256, 256>>>(labels, n_ctx);
    classsum_kernel<<<dim3(C_CLASSES, DDIM / 256), 256>>>(ctx);
    finalize_kernel<<<C_CLASSES, 256>>>(means_out);

    // join: GEMM needs both branches
    cudaStreamWaitEvent(0, s_join, 0);
    gemm_mma_kernel<<<dim3(C_CLASSES / NT, n_tgt / MT), 256, SMEM_BYTES>>>(logits);
}

// round 16
// speedup vs baseline: 1.0294x; 1.0004x over previous
#include <cuda_runtime.h>
#include <cuda_fp16.h>
#include <math.h>
#include <stdint.h>

#define C_CLASSES 512
#define DDIM      1024
#define EPS_F     1e-30f
#define SCALE_F   50.0f
#define MAX_N     65536
#define NHBLK     64

// ---------------- scratch (device globals; no allocations allowed) ----------------
__device__ float  g_sums[C_CLASSES * DDIM];
__device__ __half g_bh[C_CLASSES * DDIM];          // scaled means fp16, [N][K]
__device__ __half g_ah[(size_t)MAX_N * DDIM];      // targets fp16, [M][K]
__device__ float  g_tinv[MAX_N];
__device__ int    g_hist_part[NHBLK * C_CLASSES];  // per-block partial histograms
__device__ int    g_counts_i[C_CLASSES];
__device__ int    g_cursor[C_CLASSES];
__device__ int    g_offsets[C_CLASSES + 1];
__device__ int    g_idx[MAX_N];

// ---------------- PTX helpers (sm_80+ baseline features only) ----------------
__device__ __forceinline__ uint32_t smem_u32(const void* p) {
    uint32_t a;
    asm("{ .reg .u64 t; cvta.to.shared.u64 t, %1; cvt.u32.u64 %0, t; }" : "=r"(a) : "l"(p));
    return a;
}
#define CP_ASYNC16(dst, src) \
    asm volatile("cp.async.cg.shared.global [%0], [%1], 16;" :: "r"((uint32_t)(dst)), "l"(src))
#define CP_COMMIT() asm volatile("cp.async.commit_group;" ::: "memory")
#define CP_WAIT(n)  asm volatile("cp.async.wait_group %0;" :: "n"(n) : "memory")

__device__ __forceinline__ void ldsm_x4(uint32_t* r, uint32_t addr) {
    asm volatile("ldmatrix.sync.aligned.m8n8.x4.shared.b16 {%0,%1,%2,%3}, [%4];"
                 : "=r"(r[0]), "=r"(r[1]), "=r"(r[2]), "=r"(r[3]) : "r"(addr));
}
__device__ __forceinline__ void mma16816(float* c, const uint32_t* a, const uint32_t* b) {
    asm volatile("mma.sync.aligned.m16n8k16.row.col.f32.f16.f16.f32 "
                 "{%0,%1,%2,%3}, {%4,%5,%6,%7}, {%8,%9}, {%0,%1,%2,%3};"
                 : "+f"(c[0]), "+f"(c[1]), "+f"(c[2]), "+f"(c[3])
                 : "r"(a[0]), "r"(a[1]), "r"(a[2]), "r"(a[3]), "r"(b[0]), "r"(b[1]));
}
// 128B-row XOR swizzle: 16B column index c ^= (row & 7)
#define SWZ(o) ((o) ^ (((o) >> 3) & 0x70))

// ---------------- histogram of labels (64 blocks, partials; no zeroing needed) ----
__global__ void count_kernel(const int* __restrict__ labels, int n) {
    __shared__ int hist[C_CLASSES];
    for (int i = threadIdx.x; i < C_CLASSES; i += blockDim.x) hist[i] = 0;
    __syncthreads();
    for (int i = blockIdx.x * blockDim.x + threadIdx.x; i < n; i += gridDim.x * blockDim.x)
        atomicAdd(&hist[labels[i]], 1);
    __syncthreads();
    for (int i = threadIdx.x; i < C_CLASSES; i += blockDim.x)
        g_hist_part[blockIdx.x * C_CLASSES + i] = hist[i];
}

// ---------------- sum partials (ILP-4) + exclusive scan (1 block) ----------------
__global__ void scan_kernel() {
    __shared__ int tmp[C_CLASSES];
    int t = threadIdx.x;
    int v0 = 0, v1 = 0, v2 = 0, v3 = 0;
#pragma unroll
    for (int b = 0; b < NHBLK; b += 4) {
        v0 += g_hist_part[(b + 0) * C_CLASSES + t];
        v1 += g_hist_part[(b + 1) * C_CLASSES + t];
        v2 += g_hist_part[(b + 2) * C_CLASSES + t];
        v3 += g_hist_part[(b + 3) * C_CLASSES + t];
    }
    int v = (v0 + v1) + (v2 + v3);
    tmp[t] = v;
    g_counts_i[t] = v;
    __syncthreads();
    for (int off = 1; off < C_CLASSES; off <<= 1) {
        int x = (t >= off) ? tmp[t - off] : 0;
        __syncthreads();
        tmp[t] += x;
        __syncthreads();
    }
    g_offsets[t] = tmp[t] - v;
    g_cursor[t]  = tmp[t] - v;
    if (t == C_CLASSES - 1) g_offsets[C_CLASSES] = tmp[t];
}

// ---------------- scatter row indices into class buckets (512 blocks, 2/thread) ----
__global__ void scatter_kernel(const int* __restrict__ labels, int n) {
    int base = blockIdx.x * 512 + threadIdx.x;
#pragma unroll
    for (int p = 0; p < 2; p++) {
        int i = base + p * 256;
        if (i < n) {
            int p2 = atomicAdd(&g_cursor[labels[i]], 1);
            g_idx[p2] = i;
        }
    }
}

// ---------------- per-class gather + register accumulation (8 rows in flight) ------
__global__ void classsum_kernel(const float* __restrict__ ctx) {
    const int c   = blockIdx.x;
    const int col = blockIdx.y * 256 + threadIdx.x;
    const int beg = g_offsets[c];
    const int end = g_offsets[c + 1];

    float a0 = 0.f, a1 = 0.f, a2 = 0.f, a3 = 0.f;
    float a4 = 0.f, a5 = 0.f, a6 = 0.f, a7 = 0.f;
    int i = beg;
    for (; i + 7 < end; i += 8) {
        int r0 = g_idx[i],     r1 = g_idx[i + 1], r2 = g_idx[i + 2], r3 = g_idx[i + 3];
        int r4 = g_idx[i + 4], r5 = g_idx[i + 5], r6 = g_idx[i + 6], r7 = g_idx[i + 7];
        a0 += ctx[(size_t)r0 * DDIM + col];
        a1 += ctx[(size_t)r1 * DDIM + col];
        a2 += ctx[(size_t)r2 * DDIM + col];
        a3 += ctx[(size_t)r3 * DDIM + col];
        a4 += ctx[(size_t)r4 * DDIM + col];
        a5 += ctx[(size_t)r5 * DDIM + col];
        a6 += ctx[(size_t)r6 * DDIM + col];
        a7 += ctx[(size_t)r7 * DDIM + col];
    }
    for (; i < end; i++) a0 += ctx[(size_t)g_idx[i] * DDIM + col];
    g_sums[(size_t)c * DDIM + col] = ((a0 + a1) + (a2 + a3)) + ((a4 + a5) + (a6 + a7));
}

// ---------------- finalize: means -> d_out; scaled fp16 B -> g_bh ----------------
__global__ void finalize_kernel(float* __restrict__ means_out) {
    const int c   = blockIdx.x;
    const int tid = threadIdx.x;
    const float inv = 1.f / fmaxf((float)g_counts_i[c], 1.f);

    float m[4];
    float ss = 0.f;
#pragma unroll
    for (int j = 0; j < 4; j++) {
        int d = tid + 256 * j;
        float v = g_sums[(size_t)c * DDIM + d] * inv;
        m[j] = v;
        means_out[(size_t)c * DDIM + d] = v;
        ss += v * v;
    }
    __shared__ float red[8];
#pragma unroll
    for (int o = 16; o > 0; o >>= 1) ss += __shfl_xor_sync(0xffffffffu, ss, o);
    if ((tid & 31) == 0) red[tid >> 5] = ss;
    __syncthreads();
    __shared__ float s_scale;
    if (tid == 0) {
        float tot = 0.f;
#pragma unroll
        for (int k = 0; k < 8; k++) tot += red[k];
        s_scale = SCALE_F / fmaxf(sqrtf(tot), EPS_F);
    }
    __syncthreads();
    const float sc = s_scale;
#pragma unroll
    for (int j = 0; j < 4; j++) {
        int d = tid + 256 * j;
        g_bh[(size_t)c * DDIM + d] = __float2half_rn(m[j] * sc);
    }
}

// ---------------- fused: target fp16 convert + inverse norms (one warp per row) ----------------
__global__ void quant_a_kernel(const float4* __restrict__ tgt4, int n_tgt) {
    int w    = (blockIdx.x * blockDim.x + threadIdx.x) >> 5;
    int lane = threadIdx.x & 31;
    if (w >= n_tgt) return;
    const float4* row = tgt4 + (size_t)w * (DDIM / 4);
    uint2* hrow = (uint2*)(g_ah + (size_t)w * DDIM);
    float ss = 0.f;
#pragma unroll
    for (int j = 0; j < 8; j++) {
        int e4 = lane + 32 * j;
        float4 v = row[e4];
        ss += v.x * v.x + v.y * v.y + v.z * v.z + v.w * v.w;
        __half2 h0 = __floats2half2_rn(v.x, v.y);
        __half2 h1 = __floats2half2_rn(v.z, v.w);
        uint2 hu;
        hu.x = *reinterpret_cast<uint32_t*>(&h0);
        hu.y = *reinterpret_cast<uint32_t*>(&h1);
        hrow[e4] = hu;
    }
#pragma unroll
    for (int o = 16; o > 0; o >>= 1) ss += __shfl_xor_sync(0xffffffffu, ss, o);
    if (lane == 0) g_tinv[w] = 1.f / fmaxf(sqrtf(ss), EPS_F);
}

// ---------------- fp16 HMMA GEMM (measured 166us config, FROZEN): out = A B^T * tinv ------
// CTA tile 128x128, 256 threads, 8 warps (4m x 2n), warp tile 32x64.
// K-chunk 64 (128B rows, SW128 swizzle), 3 stages of 32KB -> 2 CTAs/SM.
#define MT   128
#define NT   128
#define KC   64
#define NC   (DDIM / KC)             // 16
#define OFF_A    0
#define OFF_B    16384
#define STAGE    32768
#define NSTAGE   3
#define SMEM_BYTES (NSTAGE * STAGE + 1024)

__device__ __forceinline__ void load_chunk(uint32_t stage, int m0, int n0, int gk0, int tid) {
#pragma unroll
    for (int p = 0; p < 4; p++) {
        int i = tid + p * 256;
        int row = i >> 3, c16 = i & 7;
        uint32_t off = SWZ((uint32_t)row * 128 + (uint32_t)c16 * 16);
        CP_ASYNC16(stage + OFF_A + off,
                   (const char*)(g_ah + (size_t)(m0 + row) * DDIM + gk0) + c16 * 16);
    }
#pragma unroll
    for (int p = 0; p < 4; p++) {
        int i = tid + p * 256;
        int row = i >> 3, c16 = i & 7;
        uint32_t off = SWZ((uint32_t)row * 128 + (uint32_t)c16 * 16);
        CP_ASYNC16(stage + OFF_B + off,
                   (const char*)(g_bh + (size_t)(n0 + row) * DDIM + gk0) + c16 * 16);
    }
    CP_COMMIT();
}

__global__ void __launch_bounds__(256, 2) gemm_mma_kernel(float* __restrict__ out) {
    extern __shared__ char dsm[];
    uint32_t sb = (smem_u32(dsm) + 1023) & ~1023u;

    const int tid  = threadIdx.x;
    const int wid  = tid >> 5;
    const int lane = tid & 31;
    const int wm   = wid >> 1;            // 0..3 (m)
    const int wn   = wid & 1;             // 0..1 (n)
    const int n0 = blockIdx.x * NT;
    const int m0 = blockIdx.y * MT;

    float acc[2][8][4];
#pragma unroll
    for (int a = 0; a < 2; a++)
#pragma unroll
        for (int b = 0; b < 8; b++)
#pragma unroll
            for (int c = 0; c < 4; c++) acc[a][b][c] = 0.f;

    // prologue: 2 chunks in flight
    load_chunk(sb + 0 * STAGE, m0, n0, 0, tid);
    load_chunk(sb + 1 * STAGE, m0, n0, KC, tid);

    // lane pieces
    const int a_r  = (lane & 15);
    const int a_kh = (lane >> 4);
    const int b_r  = (lane & 7) + ((lane >> 4) << 3);
    const int b_kh = (lane >> 3) & 1;

    int stg = 0;
    for (int c = 0; c < NC; c++) {
        if (c < NC - 1) CP_WAIT(1); else CP_WAIT(0);
        __syncthreads();
        uint32_t stage = sb + (uint32_t)stg * STAGE;

#pragma unroll
        for (int s = 0; s < 4; s++) {     // 4 k16 slices per 64-wide chunk
            uint32_t af[2][4], bf[4][4];
#pragma unroll
            for (int mt = 0; mt < 2; mt++) {
                int row = wm * 32 + mt * 16 + a_r;
                uint32_t c16 = (uint32_t)((s * 2 + a_kh) ^ (row & 7));
                ldsm_x4(af[mt], stage + OFF_A + (uint32_t)row * 128 + c16 * 16);
            }
#pragma unroll
            for (int nt = 0; nt < 4; nt++) {
                int row = wn * 64 + nt * 16 + b_r;
                uint32_t c16 = (uint32_t)((s * 2 + b_kh) ^ (row & 7));
                ldsm_x4(bf[nt], stage + OFF_B + (uint32_t)row * 128 + c16 * 16);
            }
            // 16 independent MMAs (acc reuse distance = 16)
#pragma unroll
            for (int mt = 0; mt < 2; mt++)
#pragma unroll
                for (int nt = 0; nt < 4; nt++) {
                    mma16816(acc[mt][nt * 2 + 0], af[mt], &bf[nt][0]);
                    mma16816(acc[mt][nt * 2 + 1], af[mt], &bf[nt][2]);
                }
        }

        if (c + 2 < NC) {
            int nstg = stg + 2; if (nstg >= NSTAGE) nstg -= NSTAGE;
            load_chunk(sb + (uint32_t)nstg * STAGE, m0, n0, (c + 2) * KC, tid);
        }
        if (++stg == NSTAGE) stg = 0;
    }

    // epilogue: scale by 1/||t|| and store
    const int qrow = lane >> 2;
    const int qcol = (lane & 3) * 2;
#pragma unroll
    for (int mt = 0; mt < 2; mt++) {
        int r0 = m0 + wm * 32 + mt * 16 + qrow;
        int r1 = r0 + 8;
        float t0 = g_tinv[r0], t1 = g_tinv[r1];
        float* p0 = out + (size_t)r0 * C_CLASSES + n0 + wn * 64 + qcol;
        float* p1 = out + (size_t)r1 * C_CLASSES + n0 + wn * 64 + qcol;
#pragma unroll
        for (int nf = 0; nf < 8; nf++) {
            float2 v0, v1;
            v0.x = acc[mt][nf][0] * t0; v0.y = acc[mt][nf][1] * t0;
            v1.x = acc[mt][nf][2] * t1; v1.y = acc[mt][nf][3] * t1;
            *(float2*)(p0 + nf * 8) = v0;
            *(float2*)(p1 + nf * 8) = v1;
        }
    }
}

// ---------------- launch (side-stream fork/join for prep overlap) ----------------
extern "C" void kernel_launch(void* const* d_in, const int* in_sizes, int n_in,
                              void* d_out, int out_size) {
    const float* ctx    = (const float*)d_in[0];
    const int*   labels = (const int*)d_in[1];
    const float* tgt    = (const float*)d_in[2];
    const int n_ctx = in_sizes[1];
    const int n_tgt = in_sizes[2] / DDIM;

    float* logits    = (float*)d_out;
    float* means_out = (float*)d_out + (size_t)n_tgt * C_CLASSES;

    static cudaStream_t s_side = nullptr;
    static cudaEvent_t  s_fork = nullptr, s_join = nullptr;
    if (!s_side) {
        cudaStreamCreateWithFlags(&s_side, cudaStreamNonBlocking);
        cudaEventCreateWithFlags(&s_fork, cudaEventDisableTiming);
        cudaEventCreateWithFlags(&s_join, cudaEventDisableTiming);
    }
    cudaFuncSetAttribute(gemm_mma_kernel, cudaFuncAttributeMaxDynamicSharedMemorySize, SMEM_BYTES);

    // fork: target fp16 convert runs concurrently with the class-means chain
    cudaEventRecord(s_fork, 0);
    cudaStreamWaitEvent(s_side, s_fork, 0);
    quant_a_kernel<<<(n_tgt + 7) / 8, 256, 0, s_side>>>((const float4*)tgt, n_tgt);
    cudaEventRecord(s_join, s_side);

    count_kernel<<<NHBLK, 256>>>(labels, n_ctx);
    scan_kernel<<<1, C_CLASSES>>>();
    scatter_kernel<<<(n_ctx + 511) / 512, 256>>>(labels, n_ctx);
    classsum_kernel<<<dim3(C_CLASSES, DDIM / 256), 256>>>(ctx);
    finalize_kernel<<<C_CLASSES, 256>>>(means_out);

    // join: GEMM needs both branches
    cudaStreamWaitEvent(0, s_join, 0);
    gemm_mma_kernel<<<dim3(C_CLASSES / NT, n_tgt / MT), 256, SMEM_BYTES>>>(logits);
}